// round 13
// baseline (speedup 1.0000x reference)
#include <cuda_runtime.h>
#include <math.h>
#include <stdint.h>

typedef unsigned long long ull;

#define NTOK 4096
#define DIMF 384
#define NH   6
#define HD   64
#define NSPLIT 3          // key-tile splits: 22/21/21 of 64 tiles

// STATICS BUDGET: keep total module statics <= ~31.7 MB (proven passing).
// Crossing ~32 MiB maps a second 128 MiB arena and trips the harness guard
// (established rounds 6-9). Split 0's partial goes into d_out instead of a
// third g_po slot for exactly this reason.
__device__ float g_q[(size_t)NH * NTOK * HD];
__device__ float g_k[(size_t)NH * NTOK * HD];
__device__ float g_v[(size_t)NH * HD * NTOK];        // TRANSPOSED: [h][d][token]
__device__ float g_po[(size_t)2 * NH * NTOK * HD];   // splits 1,2 partials
__device__ float g_ls[(size_t)NSPLIT * NH * NTOK];   // all 3 row-sum sets

// ---------------- helpers ----------------
__device__ __forceinline__ uint32_t smem_u32(const void* p) {
    uint32_t a;
    asm("{ .reg .u64 t; cvta.to.shared.u64 t, %1; cvt.u32.u64 %0, t; }"
        : "=r"(a) : "l"(p));
    return a;
}
__device__ __forceinline__ float to_tf32(float x) {
    uint32_t r;
    asm("cvt.rna.tf32.f32 %0, %1;" : "=r"(r) : "f"(x));
    return __uint_as_float(r);
}
__device__ __forceinline__ void mma8(float& d0, float& d1, float& d2, float& d3,
                                     uint32_t a0, uint32_t a1, uint32_t a2, uint32_t a3,
                                     uint32_t b0, uint32_t b1) {
    asm volatile("mma.sync.aligned.m16n8k8.row.col.f32.tf32.tf32.f32 "
                 "{%0,%1,%2,%3}, {%4,%5,%6,%7}, {%8,%9}, {%0,%1,%2,%3};"
                 : "+f"(d0), "+f"(d1), "+f"(d2), "+f"(d3)
                 : "r"(a0), "r"(a1), "r"(a2), "r"(a3), "r"(b0), "r"(b1));
}
#define CP_ASYNC16(sdst, gsrc) \
    asm volatile("cp.async.cg.shared.global [%0], [%1], 16;" \
                 :: "r"(sdst), "l"(gsrc) : "memory")
#define CP_COMMIT()  asm volatile("cp.async.commit_group;" ::: "memory")
#define CP_WAIT0()   asm volatile("cp.async.wait_group 0;" ::: "memory")

// ---------------- QKV GEMM via tf32 mma.sync (round-9 proven, 47.6us) ----------------
#define QG_STR  36
#define QG_XS   0
#define QG_WS   (64 * QG_STR * 4)
#define QG_TOTAL (2 * 64 * QG_STR * 4)            // 18432

__global__ __launch_bounds__(256) void qkv_mma_kernel(
    const float* __restrict__ x, const float* __restrict__ w,
    const float* __restrict__ bias)
{
    extern __shared__ char smem[];
    float* Xs = reinterpret_cast<float*>(smem + QG_XS);
    float* Ws = reinterpret_cast<float*>(smem + QG_WS);

    const int bj = blockIdx.x * 64;
    const int bm = blockIdx.y * 64;
    const int tid  = threadIdx.x;
    const int warp = tid >> 5, lane = tid & 31;
    const int quad = lane >> 2, qq = lane & 3;
    const int wm = warp & 3, wn = warp >> 2;
    const int r0l = wm * 16 + quad;
    const int nbase = wn * 32;

    const int srow0 = tid >> 3, sc4 = (tid & 7) * 4;
    const int srow1 = srow0 + 32;

    float c[4][4];
    #pragma unroll
    for (int nb = 0; nb < 4; nb++)
        c[nb][0] = c[nb][1] = c[nb][2] = c[nb][3] = 0.f;

    #pragma unroll 1
    for (int ck = 0; ck < DIMF / 32; ck++) {
        const int k0 = ck * 32;
        float4 xv0 = *reinterpret_cast<const float4*>(x + (size_t)(bm + srow0) * DIMF + k0 + sc4);
        float4 xv1 = *reinterpret_cast<const float4*>(x + (size_t)(bm + srow1) * DIMF + k0 + sc4);
        float4 wv0 = *reinterpret_cast<const float4*>(w + (size_t)(bj + srow0) * DIMF + k0 + sc4);
        float4 wv1 = *reinterpret_cast<const float4*>(w + (size_t)(bj + srow1) * DIMF + k0 + sc4);
        __syncthreads();
        *reinterpret_cast<float4*>(Xs + srow0 * QG_STR + sc4) =
            make_float4(to_tf32(xv0.x), to_tf32(xv0.y), to_tf32(xv0.z), to_tf32(xv0.w));
        *reinterpret_cast<float4*>(Xs + srow1 * QG_STR + sc4) =
            make_float4(to_tf32(xv1.x), to_tf32(xv1.y), to_tf32(xv1.z), to_tf32(xv1.w));
        *reinterpret_cast<float4*>(Ws + srow0 * QG_STR + sc4) =
            make_float4(to_tf32(wv0.x), to_tf32(wv0.y), to_tf32(wv0.z), to_tf32(wv0.w));
        *reinterpret_cast<float4*>(Ws + srow1 * QG_STR + sc4) =
            make_float4(to_tf32(wv1.x), to_tf32(wv1.y), to_tf32(wv1.z), to_tf32(wv1.w));
        __syncthreads();

        uint32_t aa[4][4];
        const uint32_t* Xu = reinterpret_cast<const uint32_t*>(Xs);
        #pragma unroll
        for (int ks = 0; ks < 4; ks++) {
            aa[ks][0] = Xu[r0l * QG_STR + ks * 8 + qq];
            aa[ks][1] = Xu[(r0l + 8) * QG_STR + ks * 8 + qq];
            aa[ks][2] = Xu[r0l * QG_STR + ks * 8 + qq + 4];
            aa[ks][3] = Xu[(r0l + 8) * QG_STR + ks * 8 + qq + 4];
        }
        const uint32_t* Wu = reinterpret_cast<const uint32_t*>(Ws);
        #pragma unroll
        for (int nb = 0; nb < 4; nb++) {
            const uint32_t* wrow = Wu + (nbase + nb * 8 + quad) * QG_STR + qq;
            #pragma unroll
            for (int ks = 0; ks < 4; ks++) {
                uint32_t b0 = wrow[ks * 8];
                uint32_t b1 = wrow[ks * 8 + 4];
                mma8(c[nb][0], c[nb][1], c[nb][2], c[nb][3],
                     aa[ks][0], aa[ks][1], aa[ks][2], aa[ks][3], b0, b1);
            }
        }
    }

    const int sec = bj / DIMF;
    const int hh  = (bj % DIMF) >> 6;
    const int m0 = bm + r0l;
    if (sec < 2) {
        float* dst = (sec == 0) ? g_q : g_k;
        #pragma unroll
        for (int nb = 0; nb < 4; nb++) {
            const int col = nbase + nb * 8 + 2 * qq;
            const float b0 = __ldg(bias + bj + col);
            const float b1 = __ldg(bias + bj + col + 1);
            *reinterpret_cast<float2*>(dst + ((size_t)hh * NTOK + m0) * HD + col) =
                make_float2(to_tf32(c[nb][0] + b0), to_tf32(c[nb][1] + b1));
            *reinterpret_cast<float2*>(dst + ((size_t)hh * NTOK + m0 + 8) * HD + col) =
                make_float2(to_tf32(c[nb][2] + b0), to_tf32(c[nb][3] + b1));
        }
    } else {
        // V -> transposed g_v[h][d][token]
        #pragma unroll
        for (int nb = 0; nb < 4; nb++) {
            const int col = nbase + nb * 8 + 2 * qq;
            const float b0 = __ldg(bias + bj + col);
            const float b1 = __ldg(bias + bj + col + 1);
            float* vd0 = g_v + ((size_t)hh * HD + col) * NTOK;
            float* vd1 = vd0 + NTOK;
            vd0[m0]     = to_tf32(c[nb][0] + b0);
            vd1[m0]     = to_tf32(c[nb][1] + b1);
            vd0[m0 + 8] = to_tf32(c[nb][2] + b0);
            vd1[m0 + 8] = to_tf32(c[nb][3] + b1);
        }
    }
}

// ---------------- fused attention: tf32 mma.sync, 3-way key split ----------------
// k-relabeled fragments (no shuffles), one barrier/tile, 3 CTAs/SM target:
// smem 71.8KB x3 = 215KB fits; ptxas reg target 85 (small spill acceptable,
// harness guard threshold is 8 KiB/thread local).
#define KROWS 64
#define KSTR  68
#define VSTR  72
#define SM_K0  0
#define SM_K1  (KROWS * KSTR * 4)                 // 17408
#define SM_V0  (2 * KROWS * KSTR * 4)             // 34816
#define SM_V1  (SM_V0 + HD * VSTR * 4)            // 53248
#define SM_RPE (SM_V1 + HD * VSTR * 4)            // 71680
#define SM_TOTAL (SM_RPE + 128)                   // 71808

__device__ __forceinline__ void stage_kv(uint32_t sK, uint32_t sV,
                                         const float* gk, const float* gvt,
                                         int k0, int tid) {
    #pragma unroll
    for (int j = 0; j < 4; j++) {
        int e = tid + j * 256;
        int row = e >> 4, d4 = (e & 15) * 4;
        // K: [key][d], row-contiguous from g_k
        CP_ASYNC16(sK + (uint32_t)(row * KSTR + d4) * 4, gk + (size_t)(k0 + row) * HD + d4);
        // V^T: [d][key], row d from g_v (stride NTOK), cols keys [k0, k0+64)
        CP_ASYNC16(sV + (uint32_t)(row * VSTR + d4) * 4, gvt + (size_t)row * NTOK + k0 + d4);
    }
}

__global__ __launch_bounds__(256, 3) void attn_kernel(
    const int* __restrict__ dist, const float* __restrict__ rpe_table,
    float* __restrict__ out)
{
    extern __shared__ char smem[];
    const uint32_t sb = smem_u32(smem);
    float* rpe  = reinterpret_cast<float*>(smem + SM_RPE);

    const int h   = blockIdx.x;
    const int q0  = blockIdx.y * 128;
    const int spl = blockIdx.z;
    const int tstart = (spl == 0) ? 0 : (spl == 1) ? 22 : 43;
    const int ntiles = (spl == 0) ? 22 : 21;
    const int kbase  = tstart * KROWS;
    const int tid  = threadIdx.x;
    const int warp = tid >> 5, lane = tid & 31;
    const int quad = lane >> 2, qq = lane & 3;

    if (tid < 21) rpe[tid] = rpe_table[tid * NH + h];

    const float* gq  = g_q + (size_t)h * NTOK * HD;
    const float* gk  = g_k + (size_t)h * NTOK * HD;
    const float* gvt = g_v + (size_t)h * HD * NTOK;

    const int r0l = warp * 16 + quad;
    const int r0  = q0 + r0l;

    // Q fragments, k-relabeled: float4 at d = 16g + 4qq supplies mma steps 2g, 2g+1
    uint32_t qa[8][4];
    #pragma unroll
    for (int g = 0; g < 4; g++) {
        float4 fr  = *reinterpret_cast<const float4*>(gq + (size_t)r0 * HD + g * 16 + 4 * qq);
        float4 fr8 = *reinterpret_cast<const float4*>(gq + (size_t)(r0 + 8) * HD + g * 16 + 4 * qq);
        qa[2*g][0]   = __float_as_uint(fr.x);   // step 2g,   k=qq,   row r
        qa[2*g][2]   = __float_as_uint(fr.y);   // step 2g,   k=qq+4, row r
        qa[2*g+1][0] = __float_as_uint(fr.z);   // step 2g+1, k=qq,   row r
        qa[2*g+1][2] = __float_as_uint(fr.w);
        qa[2*g][1]   = __float_as_uint(fr8.x);  // row r+8
        qa[2*g][3]   = __float_as_uint(fr8.y);
        qa[2*g+1][1] = __float_as_uint(fr8.z);
        qa[2*g+1][3] = __float_as_uint(fr8.w);
    }

    float o[8][4];
    #pragma unroll
    for (int nb = 0; nb < 8; nb++)
        o[nb][0] = o[nb][1] = o[nb][2] = o[nb][3] = 0.f;
    float ls0 = 0.f, ls1 = 0.f;

    const int* dr0 = dist + (size_t)r0 * NTOK;
    const int* dr1 = dr0 + 8 * NTOK;

    stage_kv(sb + SM_K0, sb + SM_V0, gk, gvt, kbase, tid);
    CP_COMMIT();

    #pragma unroll 1
    for (int kt = 0; kt < ntiles; kt++) {
        const int k0 = kbase + kt * KROWS;
        const float* Kf = reinterpret_cast<const float*>(smem + ((kt & 1) ? SM_K1 : SM_K0));
        const float* Vf = reinterpret_cast<const float*>(smem + ((kt & 1) ? SM_V1 : SM_V0));

        CP_WAIT0();
        __syncthreads();          // single barrier per tile

        if (kt + 1 < ntiles) {    // stage next tile into the other buffers now
            stage_kv(sb + ((kt & 1) ? SM_K0 : SM_K1),
                     sb + ((kt & 1) ? SM_V0 : SM_V1), gk, gvt, k0 + KROWS, tid);
            CP_COMMIT();
        }

        #pragma unroll
        for (int nb = 0; nb < 8; nb++) {
            // ---- S = Q K^T, LDS.128 K-fragments (2 mma steps per load) ----
            float s0 = 0.f, s1 = 0.f, s2 = 0.f, s3 = 0.f;
            const float* krow = Kf + (nb * 8 + quad) * KSTR + 4 * qq;
            #pragma unroll
            for (int g = 0; g < 4; g++) {
                float4 kb = *reinterpret_cast<const float4*>(krow + g * 16);
                mma8(s0, s1, s2, s3, qa[2*g][0], qa[2*g][1], qa[2*g][2], qa[2*g][3],
                     __float_as_uint(kb.x), __float_as_uint(kb.y));
                mma8(s0, s1, s2, s3, qa[2*g+1][0], qa[2*g+1][1], qa[2*g+1][2], qa[2*g+1][3],
                     __float_as_uint(kb.z), __float_as_uint(kb.w));
            }
            // ---- rpe bias + exp (no-max softmax) ----
            const int kabs = k0 + nb * 8 + 2 * qq;
            int2 d0 = *reinterpret_cast<const int2*>(dr0 + kabs);
            int2 d1 = *reinterpret_cast<const int2*>(dr1 + kabs);
            int t0 = min(max(d0.x, 0), 20), t1 = min(max(d0.y, 0), 20);
            int t2 = min(max(d1.x, 0), 20), t3 = min(max(d1.y, 0), 20);
            float p0 = __expf(s0 + rpe[t0]);   // (r,   key 2qq)
            float p1 = __expf(s1 + rpe[t1]);   // (r,   key 2qq+1)
            float p2 = __expf(s2 + rpe[t2]);   // (r+8, key 2qq)
            float p3 = __expf(s3 + rpe[t3]);   // (r+8, key 2qq+1)
            ls0 += p0 + p1;
            ls1 += p2 + p3;
            // A-fragment in place: k=qq <-> key 2qq, k=qq+4 <-> key 2qq+1
            uint32_t pa0 = __float_as_uint(to_tf32(p0));
            uint32_t pa1 = __float_as_uint(to_tf32(p2));
            uint32_t pa2 = __float_as_uint(to_tf32(p1));
            uint32_t pa3 = __float_as_uint(to_tf32(p3));

            // ---- O += P * V, LDS.64 V^T fragments (keys 2qq,2qq+1 adjacent) ----
            const float* vrow = Vf + nb * 8 + 2 * qq + quad * VSTR;
            #pragma unroll
            for (int j = 0; j < 8; j++) {
                float2 vb = *reinterpret_cast<const float2*>(vrow + j * 8 * VSTR);
                mma8(o[j][0], o[j][1], o[j][2], o[j][3], pa0, pa1, pa2, pa3,
                     __float_as_uint(vb.x), __float_as_uint(vb.y));
            }
        }
    }

    ls0 += __shfl_xor_sync(0xffffffffu, ls0, 1);
    ls0 += __shfl_xor_sync(0xffffffffu, ls0, 2);
    ls1 += __shfl_xor_sync(0xffffffffu, ls1, 1);
    ls1 += __shfl_xor_sync(0xffffffffu, ls1, 2);

    if (qq == 0) {
        g_ls[(size_t)(spl * NH + h) * NTOK + r0]     = ls0;
        g_ls[(size_t)(spl * NH + h) * NTOK + r0 + 8] = ls1;
    }
    if (spl == 0) {
        float* op0 = out + (size_t)r0 * DIMF + h * HD;
        float* op1 = op0 + (size_t)8 * DIMF;
        #pragma unroll
        for (int nb = 0; nb < 8; nb++) {
            *reinterpret_cast<float2*>(op0 + nb * 8 + 2 * qq) =
                make_float2(o[nb][0], o[nb][1]);
            *reinterpret_cast<float2*>(op1 + nb * 8 + 2 * qq) =
                make_float2(o[nb][2], o[nb][3]);
        }
    } else {
        const size_t pbase = ((size_t)((spl - 1) * NH + h) * NTOK + r0) * HD;
        #pragma unroll
        for (int nb = 0; nb < 8; nb++) {
            *reinterpret_cast<float2*>(g_po + pbase + nb * 8 + 2 * qq) =
                make_float2(o[nb][0], o[nb][1]);
            *reinterpret_cast<float2*>(g_po + pbase + 8 * HD + nb * 8 + 2 * qq) =
                make_float2(o[nb][2], o[nb][3]);
        }
    }
}

// ---------------- combine: out = (out + po0 + po1) / (l0+l1+l2) ----------------
__global__ __launch_bounds__(256) void combine_kernel(float* __restrict__ out) {
    const int idx = blockIdx.x * 256 + threadIdx.x;
    const int total4 = NTOK * DIMF / 4;
    if (idx >= total4) return;
    const int row = idx / (DIMF / 4);
    const int col = (idx % (DIMF / 4)) * 4;
    const int h = col >> 6, d = col & 63;

    const size_t p0 = ((size_t)h * NTOK + row) * HD + d;
    const size_t p1 = ((size_t)(NH + h) * NTOK + row) * HD + d;
    float4 a = *reinterpret_cast<const float4*>(out + (size_t)row * DIMF + col);
    float4 b = *reinterpret_cast<const float4*>(g_po + p0);
    float4 c = *reinterpret_cast<const float4*>(g_po + p1);
    float l = g_ls[(size_t)h * NTOK + row]
            + g_ls[(size_t)(NH + h) * NTOK + row]
            + g_ls[(size_t)(2 * NH + h) * NTOK + row];
    const float inv = 1.0f / l;
    *reinterpret_cast<float4*>(out + (size_t)row * DIMF + col) =
        make_float4((a.x + b.x + c.x) * inv, (a.y + b.y + c.y) * inv,
                    (a.z + b.z + c.z) * inv, (a.w + b.w + c.w) * inv);
}

extern "C" void kernel_launch(void* const* d_in, const int* in_sizes, int n_in,
                              void* d_out, int out_size) {
    const float* x    = (const float*)d_in[0];   // (1,4096,384)
    const int*   dist = (const int*)  d_in[1];   // (1,4096,4096)
    const float* w    = (const float*)d_in[2];   // (1152,384)
    const float* b    = (const float*)d_in[3];   // (1152,)
    const float* rpe  = (const float*)d_in[4];   // (21,6)
    float* out = (float*)d_out;                  // (1,4096,384)

    qkv_mma_kernel<<<dim3(1152/64, 4096/64), 256, QG_TOTAL>>>(x, w, b);

    cudaFuncSetAttribute(attn_kernel,
                         cudaFuncAttributeMaxDynamicSharedMemorySize, SM_TOTAL);
    attn_kernel<<<dim3(NH, NTOK/128, NSPLIT), 256, SM_TOTAL>>>(dist, rpe, out);

    combine_kernel<<<(NTOK * DIMF / 4 + 255) / 256, 256>>>(out);
}

// round 15
// speedup vs baseline: 1.4953x; 1.4953x over previous
#include <cuda_runtime.h>
#include <math.h>
#include <stdint.h>

typedef unsigned long long ull;

#define NTOK 4096
#define DIMF 384
#define NH   6
#define HD   64
#define NSPLIT 3          // key-tile splits: 22/21/21 of 64 tiles

// STATICS BUDGET: keep total module statics <= ~31.7 MB (proven passing).
// Crossing ~32 MiB maps a second 128 MiB arena and trips the harness guard
// (established rounds 6-9). Split 0's partial goes into d_out instead of a
// third g_po slot for exactly this reason.
__device__ float g_q[(size_t)NH * NTOK * HD];
__device__ float g_k[(size_t)NH * NTOK * HD];
__device__ float g_v[(size_t)NH * NTOK * HD];
__device__ float g_po[(size_t)2 * NH * NTOK * HD];   // splits 1,2 partials
__device__ float g_ls[(size_t)NSPLIT * NH * NTOK];   // all 3 row-sum sets

// ---------------- helpers ----------------
__device__ __forceinline__ uint32_t smem_u32(const void* p) {
    uint32_t a;
    asm("{ .reg .u64 t; cvta.to.shared.u64 t, %1; cvt.u32.u64 %0, t; }"
        : "=r"(a) : "l"(p));
    return a;
}
__device__ __forceinline__ float to_tf32(float x) {
    uint32_t r;
    asm("cvt.rna.tf32.f32 %0, %1;" : "=r"(r) : "f"(x));
    return __uint_as_float(r);
}
__device__ __forceinline__ void mma8(float& d0, float& d1, float& d2, float& d3,
                                     uint32_t a0, uint32_t a1, uint32_t a2, uint32_t a3,
                                     uint32_t b0, uint32_t b1) {
    asm volatile("mma.sync.aligned.m16n8k8.row.col.f32.tf32.tf32.f32 "
                 "{%0,%1,%2,%3}, {%4,%5,%6,%7}, {%8,%9}, {%0,%1,%2,%3};"
                 : "+f"(d0), "+f"(d1), "+f"(d2), "+f"(d3)
                 : "r"(a0), "r"(a1), "r"(a2), "r"(a3), "r"(b0), "r"(b1));
}
#define CP_ASYNC16(sdst, gsrc) \
    asm volatile("cp.async.cg.shared.global [%0], [%1], 16;" \
                 :: "r"(sdst), "l"(gsrc) : "memory")
#define CP_COMMIT()  asm volatile("cp.async.commit_group;" ::: "memory")
#define CP_WAIT0()   asm volatile("cp.async.wait_group 0;" ::: "memory")

// ---------------- QKV GEMM via tf32 mma.sync (round-9 proven, 47.6us) ----------------
#define QG_STR  36
#define QG_XS   0
#define QG_WS   (64 * QG_STR * 4)
#define QG_TOTAL (2 * 64 * QG_STR * 4)            // 18432

__global__ __launch_bounds__(256) void qkv_mma_kernel(
    const float* __restrict__ x, const float* __restrict__ w,
    const float* __restrict__ bias)
{
    extern __shared__ char smem[];
    float* Xs = reinterpret_cast<float*>(smem + QG_XS);
    float* Ws = reinterpret_cast<float*>(smem + QG_WS);

    const int bj = blockIdx.x * 64;
    const int bm = blockIdx.y * 64;
    const int tid  = threadIdx.x;
    const int warp = tid >> 5, lane = tid & 31;
    const int quad = lane >> 2, qq = lane & 3;
    const int wm = warp & 3, wn = warp >> 2;
    const int r0l = wm * 16 + quad;
    const int nbase = wn * 32;

    const int srow0 = tid >> 3, sc4 = (tid & 7) * 4;
    const int srow1 = srow0 + 32;

    float c[4][4];
    #pragma unroll
    for (int nb = 0; nb < 4; nb++)
        c[nb][0] = c[nb][1] = c[nb][2] = c[nb][3] = 0.f;

    #pragma unroll 1
    for (int ck = 0; ck < DIMF / 32; ck++) {
        const int k0 = ck * 32;
        float4 xv0 = *reinterpret_cast<const float4*>(x + (size_t)(bm + srow0) * DIMF + k0 + sc4);
        float4 xv1 = *reinterpret_cast<const float4*>(x + (size_t)(bm + srow1) * DIMF + k0 + sc4);
        float4 wv0 = *reinterpret_cast<const float4*>(w + (size_t)(bj + srow0) * DIMF + k0 + sc4);
        float4 wv1 = *reinterpret_cast<const float4*>(w + (size_t)(bj + srow1) * DIMF + k0 + sc4);
        __syncthreads();
        *reinterpret_cast<float4*>(Xs + srow0 * QG_STR + sc4) =
            make_float4(to_tf32(xv0.x), to_tf32(xv0.y), to_tf32(xv0.z), to_tf32(xv0.w));
        *reinterpret_cast<float4*>(Xs + srow1 * QG_STR + sc4) =
            make_float4(to_tf32(xv1.x), to_tf32(xv1.y), to_tf32(xv1.z), to_tf32(xv1.w));
        *reinterpret_cast<float4*>(Ws + srow0 * QG_STR + sc4) =
            make_float4(to_tf32(wv0.x), to_tf32(wv0.y), to_tf32(wv0.z), to_tf32(wv0.w));
        *reinterpret_cast<float4*>(Ws + srow1 * QG_STR + sc4) =
            make_float4(to_tf32(wv1.x), to_tf32(wv1.y), to_tf32(wv1.z), to_tf32(wv1.w));
        __syncthreads();

        uint32_t aa[4][4];
        const uint32_t* Xu = reinterpret_cast<const uint32_t*>(Xs);
        #pragma unroll
        for (int ks = 0; ks < 4; ks++) {
            aa[ks][0] = Xu[r0l * QG_STR + ks * 8 + qq];
            aa[ks][1] = Xu[(r0l + 8) * QG_STR + ks * 8 + qq];
            aa[ks][2] = Xu[r0l * QG_STR + ks * 8 + qq + 4];
            aa[ks][3] = Xu[(r0l + 8) * QG_STR + ks * 8 + qq + 4];
        }
        const uint32_t* Wu = reinterpret_cast<const uint32_t*>(Ws);
        #pragma unroll
        for (int nb = 0; nb < 4; nb++) {
            const uint32_t* wrow = Wu + (nbase + nb * 8 + quad) * QG_STR + qq;
            #pragma unroll
            for (int ks = 0; ks < 4; ks++) {
                uint32_t b0 = wrow[ks * 8];
                uint32_t b1 = wrow[ks * 8 + 4];
                mma8(c[nb][0], c[nb][1], c[nb][2], c[nb][3],
                     aa[ks][0], aa[ks][1], aa[ks][2], aa[ks][3], b0, b1);
            }
        }
    }

    const int sec = bj / DIMF;
    const int hh  = (bj % DIMF) >> 6;
    float* dst = (sec == 0) ? g_q : (sec == 1) ? g_k : g_v;
    const int m0 = bm + r0l;
    #pragma unroll
    for (int nb = 0; nb < 4; nb++) {
        const int col = nbase + nb * 8 + 2 * qq;
        const float b0 = __ldg(bias + bj + col);
        const float b1 = __ldg(bias + bj + col + 1);
        *reinterpret_cast<float2*>(dst + ((size_t)hh * NTOK + m0) * HD + col) =
            make_float2(to_tf32(c[nb][0] + b0), to_tf32(c[nb][1] + b1));
        *reinterpret_cast<float2*>(dst + ((size_t)hh * NTOK + m0 + 8) * HD + col) =
            make_float2(to_tf32(c[nb][2] + b0), to_tf32(c[nb][3] + b1));
    }
}

// ---------------- fused attention: tf32 mma.sync, 3-way key split ----------------
// P stays in registers (intra-quad shuffles); one barrier/tile; S accumulation
// split into two independent 4-deep mma chains for ILP.
#define KROWS 64
#define KSTR  68
#define VSTR  72
#define SM_K0  0
#define SM_K1  (KROWS * KSTR * 4)                 // 17408
#define SM_V0  (2 * KROWS * KSTR * 4)             // 34816
#define SM_V1  (SM_V0 + KROWS * VSTR * 4)         // 53248
#define SM_RPE (SM_V1 + KROWS * VSTR * 4)         // 71680
#define SM_TOTAL (SM_RPE + 128)                   // 71808

__device__ __forceinline__ void stage_kv(uint32_t sK, uint32_t sV,
                                         const float* gk, const float* gv,
                                         int k0, int tid) {
    #pragma unroll
    for (int j = 0; j < 4; j++) {
        int e = tid + j * 256;
        int row = e >> 4, d4 = (e & 15) * 4;
        CP_ASYNC16(sK + (uint32_t)(row * KSTR + d4) * 4, gk + (size_t)(k0 + row) * HD + d4);
        CP_ASYNC16(sV + (uint32_t)(row * VSTR + d4) * 4, gv + (size_t)(k0 + row) * HD + d4);
    }
}

__global__ __launch_bounds__(256, 2) void attn_kernel(
    const int* __restrict__ dist, const float* __restrict__ rpe_table,
    float* __restrict__ out)
{
    extern __shared__ char smem[];
    const uint32_t sb = smem_u32(smem);
    float* rpe  = reinterpret_cast<float*>(smem + SM_RPE);

    const int h   = blockIdx.x;
    const int q0  = blockIdx.y * 128;
    const int spl = blockIdx.z;
    const int tstart = (spl == 0) ? 0 : (spl == 1) ? 22 : 43;
    const int ntiles = (spl == 0) ? 22 : 21;
    const int kbase  = tstart * KROWS;
    const int tid  = threadIdx.x;
    const int warp = tid >> 5, lane = tid & 31;
    const int quad = lane >> 2, qq = lane & 3;
    const int sA = (lane & 28) | (qq >> 1);       // shuffle src for P cols [0,4)
    const int sB = sA + 2;                        // shuffle src for P cols [4,8)
    const bool odd = (qq & 1);

    if (tid < 21) rpe[tid] = rpe_table[tid * NH + h];

    const float* gq = g_q + (size_t)h * NTOK * HD;
    const float* gk = g_k + (size_t)h * NTOK * HD;
    const float* gv = g_v + (size_t)h * NTOK * HD;

    const int r0l = warp * 16 + quad;
    const int r0  = q0 + r0l;

    uint32_t qa[8][4];
    #pragma unroll
    for (int ks = 0; ks < 8; ks++) {
        const float* p = gq + (size_t)r0 * HD + ks * 8 + qq;
        qa[ks][0] = __float_as_uint(p[0]);
        qa[ks][1] = __float_as_uint(p[8 * HD]);
        qa[ks][2] = __float_as_uint(p[4]);
        qa[ks][3] = __float_as_uint(p[8 * HD + 4]);
    }

    float o[8][4];
    #pragma unroll
    for (int nb = 0; nb < 8; nb++)
        o[nb][0] = o[nb][1] = o[nb][2] = o[nb][3] = 0.f;
    float ls0 = 0.f, ls1 = 0.f;

    const int* dr0 = dist + (size_t)r0 * NTOK;
    const int* dr1 = dr0 + 8 * NTOK;

    stage_kv(sb + SM_K0, sb + SM_V0, gk, gv, kbase, tid);
    CP_COMMIT();

    #pragma unroll 1
    for (int kt = 0; kt < ntiles; kt++) {
        const int k0 = kbase + kt * KROWS;
        const float* Kf = reinterpret_cast<const float*>(smem + ((kt & 1) ? SM_K1 : SM_K0));
        const float* Vf = reinterpret_cast<const float*>(smem + ((kt & 1) ? SM_V1 : SM_V0));

        CP_WAIT0();
        __syncthreads();          // single barrier per tile

        if (kt + 1 < ntiles) {    // stage next tile into the other buffers now
            stage_kv(sb + ((kt & 1) ? SM_K0 : SM_K1),
                     sb + ((kt & 1) ? SM_V0 : SM_V1), gk, gv, k0 + KROWS, tid);
            CP_COMMIT();
        }

        const uint32_t* Vu = reinterpret_cast<const uint32_t*>(Vf);

        #pragma unroll
        for (int nb = 0; nb < 8; nb++) {
            // ---- S = Q K^T: two independent 4-deep mma chains ----
            float sa0 = 0.f, sa1 = 0.f, sa2 = 0.f, sa3 = 0.f;
            float sb0 = 0.f, sb1 = 0.f, sb2 = 0.f, sb3 = 0.f;
            const uint32_t* krow0 = reinterpret_cast<const uint32_t*>(
                Kf + (nb * 8 + quad) * KSTR + qq);
            #pragma unroll
            for (int ks = 0; ks < 4; ks++) {
                uint32_t b0 = krow0[ks * 8];
                uint32_t b1 = krow0[ks * 8 + 4];
                mma8(sa0, sa1, sa2, sa3, qa[ks][0], qa[ks][1], qa[ks][2], qa[ks][3], b0, b1);
                uint32_t c0 = krow0[(ks + 4) * 8];
                uint32_t c1 = krow0[(ks + 4) * 8 + 4];
                mma8(sb0, sb1, sb2, sb3, qa[ks+4][0], qa[ks+4][1], qa[ks+4][2], qa[ks+4][3], c0, c1);
            }
            float s0 = sa0 + sb0, s1 = sa1 + sb1;
            float s2 = sa2 + sb2, s3 = sa3 + sb3;
            // ---- rpe bias + exp (no-max softmax) ----
            const int kabs = k0 + nb * 8 + 2 * qq;
            int2 d0 = *reinterpret_cast<const int2*>(dr0 + kabs);
            int2 d1 = *reinterpret_cast<const int2*>(dr1 + kabs);
            int t0 = min(max(d0.x, 0), 20), t1 = min(max(d0.y, 0), 20);
            int t2 = min(max(d1.x, 0), 20), t3 = min(max(d1.y, 0), 20);
            float p0 = __expf(s0 + rpe[t0]);
            float p1 = __expf(s1 + rpe[t1]);
            float p2 = __expf(s2 + rpe[t2]);
            float p3 = __expf(s3 + rpe[t3]);
            ls0 += p0 + p1;
            ls1 += p2 + p3;
            p0 = to_tf32(p0); p1 = to_tf32(p1);
            p2 = to_tf32(p2); p3 = to_tf32(p3);

            // ---- accumulator layout -> A-fragment layout (intra-quad shuffles) ----
            float g0 = __shfl_sync(0xffffffffu, p0, sA);
            float g1 = __shfl_sync(0xffffffffu, p1, sA);
            float h0 = __shfl_sync(0xffffffffu, p0, sB);
            float h1 = __shfl_sync(0xffffffffu, p1, sB);
            uint32_t pa0 = __float_as_uint(odd ? g1 : g0);   // P(r,   qq)
            uint32_t pa2 = __float_as_uint(odd ? h1 : h0);   // P(r,   qq+4)
            float g2 = __shfl_sync(0xffffffffu, p2, sA);
            float g3 = __shfl_sync(0xffffffffu, p3, sA);
            float h2 = __shfl_sync(0xffffffffu, p2, sB);
            float h3 = __shfl_sync(0xffffffffu, p3, sB);
            uint32_t pa1 = __float_as_uint(odd ? g3 : g2);   // P(r+8, qq)
            uint32_t pa3 = __float_as_uint(odd ? h3 : h2);   // P(r+8, qq+4)

            // ---- O += P(block nb) * V(block nb) ----
            const uint32_t* vrow0 = Vu + (nb * 8 + qq) * VSTR + quad;
            const uint32_t* vrow1 = Vu + (nb * 8 + qq + 4) * VSTR + quad;
            #pragma unroll
            for (int j = 0; j < 8; j++) {
                uint32_t b0 = vrow0[j * 8];
                uint32_t b1 = vrow1[j * 8];
                mma8(o[j][0], o[j][1], o[j][2], o[j][3], pa0, pa1, pa2, pa3, b0, b1);
            }
        }
    }

    ls0 += __shfl_xor_sync(0xffffffffu, ls0, 1);
    ls0 += __shfl_xor_sync(0xffffffffu, ls0, 2);
    ls1 += __shfl_xor_sync(0xffffffffu, ls1, 1);
    ls1 += __shfl_xor_sync(0xffffffffu, ls1, 2);

    if (qq == 0) {
        g_ls[(size_t)(spl * NH + h) * NTOK + r0]     = ls0;
        g_ls[(size_t)(spl * NH + h) * NTOK + r0 + 8] = ls1;
    }
    if (spl == 0) {
        float* op0 = out + (size_t)r0 * DIMF + h * HD;
        float* op1 = op0 + (size_t)8 * DIMF;
        #pragma unroll
        for (int nb = 0; nb < 8; nb++) {
            *reinterpret_cast<float2*>(op0 + nb * 8 + 2 * qq) =
                make_float2(o[nb][0], o[nb][1]);
            *reinterpret_cast<float2*>(op1 + nb * 8 + 2 * qq) =
                make_float2(o[nb][2], o[nb][3]);
        }
    } else {
        const size_t pbase = ((size_t)((spl - 1) * NH + h) * NTOK + r0) * HD;
        #pragma unroll
        for (int nb = 0; nb < 8; nb++) {
            *reinterpret_cast<float2*>(g_po + pbase + nb * 8 + 2 * qq) =
                make_float2(o[nb][0], o[nb][1]);
            *reinterpret_cast<float2*>(g_po + pbase + 8 * HD + nb * 8 + 2 * qq) =
                make_float2(o[nb][2], o[nb][3]);
        }
    }
}

// ---------------- combine: out = (out + po0 + po1) / (l0+l1+l2) ----------------
__global__ __launch_bounds__(256) void combine_kernel(float* __restrict__ out) {
    const int idx = blockIdx.x * 256 + threadIdx.x;
    const int total4 = NTOK * DIMF / 4;
    if (idx >= total4) return;
    const int row = idx / (DIMF / 4);
    const int col = (idx % (DIMF / 4)) * 4;
    const int h = col >> 6, d = col & 63;

    const size_t p0 = ((size_t)h * NTOK + row) * HD + d;
    const size_t p1 = ((size_t)(NH + h) * NTOK + row) * HD + d;
    float4 a = *reinterpret_cast<const float4*>(out + (size_t)row * DIMF + col);
    float4 b = *reinterpret_cast<const float4*>(g_po + p0);
    float4 c = *reinterpret_cast<const float4*>(g_po + p1);
    float l = g_ls[(size_t)h * NTOK + row]
            + g_ls[(size_t)(NH + h) * NTOK + row]
            + g_ls[(size_t)(2 * NH + h) * NTOK + row];
    const float inv = 1.0f / l;
    *reinterpret_cast<float4*>(out + (size_t)row * DIMF + col) =
        make_float4((a.x + b.x + c.x) * inv, (a.y + b.y + c.y) * inv,
                    (a.z + b.z + c.z) * inv, (a.w + b.w + c.w) * inv);
}

extern "C" void kernel_launch(void* const* d_in, const int* in_sizes, int n_in,
                              void* d_out, int out_size) {
    const float* x    = (const float*)d_in[0];   // (1,4096,384)
    const int*   dist = (const int*)  d_in[1];   // (1,4096,4096)
    const float* w    = (const float*)d_in[2];   // (1152,384)
    const float* b    = (const float*)d_in[3];   // (1152,)
    const float* rpe  = (const float*)d_in[4];   // (21,6)
    float* out = (float*)d_out;                  // (1,4096,384)

    qkv_mma_kernel<<<dim3(1152/64, 4096/64), 256, QG_TOTAL>>>(x, w, b);

    cudaFuncSetAttribute(attn_kernel,
                         cudaFuncAttributeMaxDynamicSharedMemorySize, SM_TOTAL);
    attn_kernel<<<dim3(NH, NTOK/128, NSPLIT), 256, SM_TOTAL>>>(dist, rpe, out);

    combine_kernel<<<(NTOK * DIMF / 4 + 255) / 256, 256>>>(out);
}